// round 6
// baseline (speedup 1.0000x reference)
#include <cuda_runtime.h>
#include <math.h>

#define N   8192
#define NZ  256
#define NC  128
#define DT_ 0.1f

// A-phase (z = W_rz @ r), 8-way column split, 4 rows per block
#define SPL_A    8
#define CHA4     (N / 4 / SPL_A)       // 256 float4 per column chunk
#define A_BLOCKS ((NZ / 4) * SPL_A)    // 512 blocks

// B-phase: persistent row-update blocks
#define B_GRID   768

// Tail (z_new / c_new), 4-way split
#define SPL_T 4
#define CHT4  (N / 4 / SPL_T)          // 512 float4

// Scratch (__device__ globals; zero-initialized at module load)
__device__ float g_r[N];
__device__ float g_zpart[SPL_A][NZ];
__device__ float g_rn[N];
__device__ float g_tpart[SPL_T][NZ + NC];
__device__ int   g_cnt[NZ + NC];
__device__ int   g_a_done;
__device__ int   g_b_done;

__inline__ __device__ float dot4(float4 a, float4 b) {
    return a.x * b.x + a.y * b.y + a.z * b.z + a.w * b.w;
}

__inline__ __device__ float block_reduce(float v) {
    __shared__ float sm[8];
    const int lane = threadIdx.x & 31;
    const int wid  = threadIdx.x >> 5;
    #pragma unroll
    for (int o = 16; o; o >>= 1) v += __shfl_down_sync(0xffffffffu, v, o);
    if (lane == 0) sm[wid] = v;
    __syncthreads();
    if (wid == 0) {
        v = (lane < 8) ? sm[lane] : 0.f;
        #pragma unroll
        for (int o = 4; o; o >>= 1) v += __shfl_down_sync(0xffffffffu, v, o);
    }
    __syncthreads();   // protect sm reuse across loop iterations
    return v;          // valid in thread 0
}

__inline__ __device__ float4 block_reduce4(float4 v) {
    __shared__ float4 sm4[8];
    const int lane = threadIdx.x & 31;
    const int wid  = threadIdx.x >> 5;
    #pragma unroll
    for (int o = 16; o; o >>= 1) {
        v.x += __shfl_down_sync(0xffffffffu, v.x, o);
        v.y += __shfl_down_sync(0xffffffffu, v.y, o);
        v.z += __shfl_down_sync(0xffffffffu, v.z, o);
        v.w += __shfl_down_sync(0xffffffffu, v.w, o);
    }
    if (lane == 0) sm4[wid] = v;
    __syncthreads();
    if (wid == 0) {
        v = (lane < 8) ? sm4[lane] : make_float4(0.f, 0.f, 0.f, 0.f);
        #pragma unroll
        for (int o = 4; o; o >>= 1) {
            v.x += __shfl_down_sync(0xffffffffu, v.x, o);
            v.y += __shfl_down_sync(0xffffffffu, v.y, o);
            v.z += __shfl_down_sync(0xffffffffu, v.z, o);
            v.w += __shfl_down_sync(0xffffffffu, v.w, o);
        }
    }
    return v;
}

// ---------------------------------------------------------------------------
// Merged main kernel.
//  Blocks [0, A_BLOCKS):      r = tanh(x+b) (split-owned chunks) + split-K
//                             partials of z = W_rz @ r; signal g_a_done.
//  Blocks [A_BLOCKS, +B_GRID): persistent row-update workers. Spin for A,
//                             stage r/z/eps/c in smem, then loop rows strided
//                             by B_GRID computing x_new, r_new.
// ---------------------------------------------------------------------------
__global__ void __launch_bounds__(256) k_main(
    const float* __restrict__ x,    const float* __restrict__ b,
    const float* __restrict__ W_rz, const float* __restrict__ W_rr,
    const float* __restrict__ W_zr, const float* __restrict__ W_cr,
    const float* __restrict__ W_epsr,
    const float* __restrict__ eps,  const float* __restrict__ c,
    float* __restrict__ out)
{
    const int tid = threadIdx.x;

    if (blockIdx.x < A_BLOCKS) {
        // ----- A phase: z partials + g_r -----
        const int s    = blockIdx.x & (SPL_A - 1);
        const int rg   = blockIdx.x >> 3;      // 0..63
        const int row0 = rg * 4;
        const int c4   = s * CHA4 + tid;       // one float4 per thread

        float4 xv = ((const float4*)x)[c4];
        float4 bv = ((const float4*)b)[c4];
        float4 r0;
        r0.x = tanhf(xv.x + bv.x); r0.y = tanhf(xv.y + bv.y);
        r0.z = tanhf(xv.z + bv.z); r0.w = tanhf(xv.w + bv.w);
        if (rg == 0) ((float4*)g_r)[c4] = r0;

        const float4* w0 = (const float4*)(W_rz + (size_t)(row0 + 0) * N);
        const float4* w1 = (const float4*)(W_rz + (size_t)(row0 + 1) * N);
        const float4* w2 = (const float4*)(W_rz + (size_t)(row0 + 2) * N);
        const float4* w3 = (const float4*)(W_rz + (size_t)(row0 + 3) * N);
        float4 acc;
        acc.x = dot4(__ldcs(&w0[c4]), r0);
        acc.y = dot4(__ldcs(&w1[c4]), r0);
        acc.z = dot4(__ldcs(&w2[c4]), r0);
        acc.w = dot4(__ldcs(&w3[c4]), r0);
        acc = block_reduce4(acc);
        if (tid == 0) {
            g_zpart[s][row0 + 0] = acc.x;
            g_zpart[s][row0 + 1] = acc.y;
            g_zpart[s][row0 + 2] = acc.z;
            g_zpart[s][row0 + 3] = acc.w;
            __threadfence();
            atomicAdd(&g_a_done, 1);
        }
        return;
    }

    // ----- B phase: persistent row-update workers -----
    __shared__ float4 sr[N / 4];   // 32 KB: r vector
    __shared__ float  sz[NZ];      // z (summed)
    __shared__ float  se[NZ];      // eps
    __shared__ float  sc[NC];      // c

    if (tid == 0) {
        while (*(volatile int*)&g_a_done < A_BLOCKS) { }
        __threadfence();
    }
    __syncthreads();

    // Stage r (via L2 — coherent with A's writes), z, eps, c into smem
    #pragma unroll
    for (int i = tid; i < N / 4; i += 256) {
        const float4* p = &((const float4*)g_r)[i];
        sr[i] = __ldcg(p);
    }
    if (tid < NZ) {
        float zv = 0.f;
        #pragma unroll
        for (int s = 0; s < SPL_A; s++) zv += __ldcg(&g_zpart[s][tid]);
        sz[tid] = zv;
        se[tid] = eps[tid];
        if (tid < NC) sc[tid] = c[tid];
    }
    __syncthreads();

    const int b0 = blockIdx.x - A_BLOCKS;
    for (int row = b0; row < N; row += B_GRID) {
        const float4* __restrict__ w = (const float4*)(W_rr + (size_t)row * N);
        float a0 = 0.f, a1 = 0.f, a2 = 0.f, a3 = 0.f;
        #pragma unroll
        for (int i = 0; i < 8; i++) {
            const int k = tid + i * 256;
            float d = dot4(__ldcs(&w[k]), sr[k]);
            if ((i & 3) == 0) a0 += d;
            else if ((i & 3) == 1) a1 += d;
            else if ((i & 3) == 2) a2 += d;
            else a3 += d;
        }
        float acc = (a0 + a1) + (a2 + a3);

        // Side dots on disjoint thread ranges (all vectors smem-resident)
        if (tid < 64) {                        // W_epsr row · eps
            float4 a = __ldcs(((const float4*)(W_epsr + (size_t)row * NZ)) + tid);
            acc += dot4(a, ((const float4*)se)[tid]);
        } else if (tid < 128) {                // W_zr row · z
            const int k = tid - 64;
            float4 a = __ldcs(((const float4*)(W_zr + (size_t)row * NZ)) + k);
            acc += dot4(a, ((const float4*)sz)[k]);
        } else if (tid < 160) {                // W_cr row · c
            const int k = tid - 128;
            float4 a = __ldcs(((const float4*)(W_cr + (size_t)row * NC)) + k);
            acc += dot4(a, ((const float4*)sc)[k]);
        }

        acc = block_reduce(acc);
        if (tid == 0) {
            float xv = x[row];
            float xn = xv + DT_ * (acc - xv);
            out[row] = xn;
            float rn = tanhf(xn + b[row]);
            out[N + row] = rn;
            g_rn[row] = rn;
        }
    }

    // Reset counters for the next graph replay (last B block only; by then
    // every block has passed its spin).
    __syncthreads();
    if (tid == 0) {
        int old = atomicAdd(&g_b_done, 1);
        if (old == B_GRID - 1) {
            g_a_done = 0;
            g_b_done = 0;
        }
    }
}

// ---------------------------------------------------------------------------
// Tail: split-K z_new / c_new against r_new, finalize fused via per-row
// atomic counter. Deterministic: partials summed in fixed split order.
// ---------------------------------------------------------------------------
__global__ void __launch_bounds__(256) k_tail(
    const float* __restrict__ W_rz, const float* __restrict__ W_rc,
    const float* __restrict__ z_tilde, float* __restrict__ out)
{
    const int s   = blockIdx.x & (SPL_T - 1);
    const int idx = blockIdx.x >> 2;
    const float* __restrict__ Wrow = (idx < NZ)
        ? (W_rz + (size_t)idx * N)
        : (W_rc + (size_t)(idx - NZ) * N);
    const float4* __restrict__ w = (const float4*)Wrow;
    const float4* __restrict__ v = (const float4*)g_rn;
    const int c4 = s * CHT4 + threadIdx.x * 2;

    float acc = dot4(__ldcs(&w[c4]), v[c4]) + dot4(__ldcs(&w[c4 + 1]), v[c4 + 1]);
    acc = block_reduce(acc);
    if (threadIdx.x == 0) {
        g_tpart[s][idx] = acc;
        __threadfence();
        int old = atomicAdd(&g_cnt[idx], 1);
        if (old == SPL_T - 1) {
            float vsum = __ldcg(&g_tpart[0][idx]) + __ldcg(&g_tpart[1][idx])
                       + __ldcg(&g_tpart[2][idx]) + __ldcg(&g_tpart[3][idx]);
            if (idx < NZ) {
                out[2 * N + idx] = vsum;                           // z_new
                out[2 * N + NZ + NC + idx] = vsum - z_tilde[idx];  // eps_new
            } else {
                out[2 * N + NZ + (idx - NZ)] = vsum;               // c_new
            }
            g_cnt[idx] = 0;   // reset for next replay
        }
    }
}

extern "C" void kernel_launch(void* const* d_in, const int* in_sizes, int n_in,
                              void* d_out, int out_size) {
    // metadata order: x, eps, c, z_tilde, W_rr, W_zr, W_cr, W_epsr, W_rz, W_rc, b
    const float* x       = (const float*)d_in[0];
    const float* eps     = (const float*)d_in[1];
    const float* c       = (const float*)d_in[2];
    const float* z_tilde = (const float*)d_in[3];
    const float* W_rr    = (const float*)d_in[4];
    const float* W_zr    = (const float*)d_in[5];
    const float* W_cr    = (const float*)d_in[6];
    const float* W_epsr  = (const float*)d_in[7];
    const float* W_rz    = (const float*)d_in[8];
    const float* W_rc    = (const float*)d_in[9];
    const float* b       = (const float*)d_in[10];
    float* out = (float*)d_out;

    k_main<<<A_BLOCKS + B_GRID, 256>>>(x, b, W_rz, W_rr, W_zr, W_cr, W_epsr,
                                       eps, c, out);
    k_tail<<<(NZ + NC) * SPL_T, 256>>>(W_rz, W_rc, z_tilde, out);
}

// round 8
// speedup vs baseline: 1.2231x; 1.2231x over previous
#include <cuda_runtime.h>
#include <math.h>

#define N   8192
#define NZ  256
#define NC  128
#define DT_ 0.1f

// k_rz: z = W_rz @ r, 8-way column split, 4 rows per block -> 512 blocks
#define SPL_A 8
#define CHA4  (N / 4 / SPL_A)          // 256 float4 per column chunk

// k_big: 4 rows per block, r staged in smem
#define ROWS_B 4
#define BIG_GRID (N / ROWS_B)          // 2048 blocks

// Scratch (__device__ globals)
__device__ float g_r[N];
__device__ float g_zpart[SPL_A][NZ];
__device__ float g_rn[N];

__inline__ __device__ float dot4(float4 a, float4 b) {
    return a.x * b.x + a.y * b.y + a.z * b.z + a.w * b.w;
}

// Block reduce for up to 512 threads (16 warps). Valid in thread 0.
__inline__ __device__ float block_reduce_w(float v, int nwarps) {
    __shared__ float sm[16];
    const int lane = threadIdx.x & 31;
    const int wid  = threadIdx.x >> 5;
    #pragma unroll
    for (int o = 16; o; o >>= 1) v += __shfl_down_sync(0xffffffffu, v, o);
    if (lane == 0) sm[wid] = v;
    __syncthreads();
    if (wid == 0) {
        v = (lane < nwarps) ? sm[lane] : 0.f;
        #pragma unroll
        for (int o = 8; o; o >>= 1) v += __shfl_down_sync(0xffffffffu, v, o);
    }
    return v;
}

// 4-wide block reduce, 8 warps (256 threads). Valid in thread 0.
__inline__ __device__ float4 block_reduce4(float4 v) {
    __shared__ float4 sm4[8];
    const int lane = threadIdx.x & 31;
    const int wid  = threadIdx.x >> 5;
    #pragma unroll
    for (int o = 16; o; o >>= 1) {
        v.x += __shfl_down_sync(0xffffffffu, v.x, o);
        v.y += __shfl_down_sync(0xffffffffu, v.y, o);
        v.z += __shfl_down_sync(0xffffffffu, v.z, o);
        v.w += __shfl_down_sync(0xffffffffu, v.w, o);
    }
    if (lane == 0) sm4[wid] = v;
    __syncthreads();
    if (wid == 0) {
        v = (lane < 8) ? sm4[lane] : make_float4(0.f, 0.f, 0.f, 0.f);
        #pragma unroll
        for (int o = 4; o; o >>= 1) {
            v.x += __shfl_down_sync(0xffffffffu, v.x, o);
            v.y += __shfl_down_sync(0xffffffffu, v.y, o);
            v.z += __shfl_down_sync(0xffffffffu, v.z, o);
            v.w += __shfl_down_sync(0xffffffffu, v.w, o);
        }
    }
    return v;
}

// ---------------------------------------------------------------------------
// Kernel 1: r = tanh(x+b) (split-owned chunks persisted by row-group 0) and
// split-K partials of z = W_rz @ r for 4 rows/block.
// Grid: 64 row-groups * 8 splits = 512 blocks, 256 threads (1 float4/thread).
// ---------------------------------------------------------------------------
__global__ void __launch_bounds__(256) k_rz(
    const float* __restrict__ x, const float* __restrict__ b,
    const float* __restrict__ W_rz)
{
    const int s    = blockIdx.x & (SPL_A - 1);
    const int rg   = blockIdx.x >> 3;
    const int row0 = rg * 4;
    const int c4   = s * CHA4 + threadIdx.x;

    float4 xv = ((const float4*)x)[c4];
    float4 bv = ((const float4*)b)[c4];
    float4 r0;
    r0.x = tanhf(xv.x + bv.x); r0.y = tanhf(xv.y + bv.y);
    r0.z = tanhf(xv.z + bv.z); r0.w = tanhf(xv.w + bv.w);
    if (rg == 0) ((float4*)g_r)[c4] = r0;

    const float4* w0 = (const float4*)(W_rz + (size_t)(row0 + 0) * N);
    const float4* w1 = (const float4*)(W_rz + (size_t)(row0 + 1) * N);
    const float4* w2 = (const float4*)(W_rz + (size_t)(row0 + 2) * N);
    const float4* w3 = (const float4*)(W_rz + (size_t)(row0 + 3) * N);
    float4 acc;
    acc.x = dot4(__ldcs(&w0[c4]), r0);
    acc.y = dot4(__ldcs(&w1[c4]), r0);
    acc.z = dot4(__ldcs(&w2[c4]), r0);
    acc.w = dot4(__ldcs(&w3[c4]), r0);
    acc = block_reduce4(acc);
    if (threadIdx.x == 0) {
        g_zpart[s][row0 + 0] = acc.x;
        g_zpart[s][row0 + 1] = acc.y;
        g_zpart[s][row0 + 2] = acc.z;
        g_zpart[s][row0 + 3] = acc.w;
    }
}

// ---------------------------------------------------------------------------
// Kernel 2: fused row update, 4 rows per block with r staged in shared memory
// (read from L2 ONCE per block instead of once per row -> 256MB -> 64MB LTS).
// Grid: 2048 blocks, 256 threads.
// ---------------------------------------------------------------------------
__global__ void __launch_bounds__(256) k_big(
    const float* __restrict__ W_rr, const float* __restrict__ W_zr,
    const float* __restrict__ W_cr, const float* __restrict__ W_epsr,
    const float* __restrict__ x,    const float* __restrict__ eps,
    const float* __restrict__ c,    const float* __restrict__ b,
    float* __restrict__ out)
{
    __shared__ float4 sr[N / 4];   // 32 KB
    __shared__ float  sz[NZ];
    __shared__ float  se[NZ];
    __shared__ float  sc[NC];

    const int tid  = threadIdx.x;
    const int row0 = blockIdx.x * ROWS_B;

    // Stage r, z (summed in fixed split order), eps, c into smem
    #pragma unroll
    for (int i = tid; i < N / 4; i += 256) sr[i] = ((const float4*)g_r)[i];
    if (tid < 64) {
        float4 q = ((const float4*)g_zpart[0])[tid];
        #pragma unroll
        for (int s = 1; s < SPL_A; s++) {
            float4 p = ((const float4*)g_zpart[s])[tid];
            q.x += p.x; q.y += p.y; q.z += p.z; q.w += p.w;
        }
        ((float4*)sz)[tid] = q;
    } else if (tid < 128) {
        ((float4*)se)[tid - 64] = ((const float4*)eps)[tid - 64];
    } else if (tid < 160) {
        ((float4*)sc)[tid - 128] = ((const float4*)c)[tid - 128];
    }
    __syncthreads();

    float racc[ROWS_B];
    #pragma unroll
    for (int rr = 0; rr < ROWS_B; rr++) {
        const int row = row0 + rr;
        const float4* __restrict__ w = (const float4*)(W_rr + (size_t)row * N);
        float a0 = 0.f, a1 = 0.f, a2 = 0.f, a3 = 0.f;
        #pragma unroll
        for (int i = 0; i < 8; i++) {
            const int k = tid + i * 256;
            float d = dot4(__ldcs(&w[k]), sr[k]);
            if ((i & 3) == 0) a0 += d;
            else if ((i & 3) == 1) a1 += d;
            else if ((i & 3) == 2) a2 += d;
            else a3 += d;
        }
        float acc = (a0 + a1) + (a2 + a3);

        // Side dots on disjoint thread ranges (vectors smem-resident)
        if (tid < 64) {
            float4 a = __ldcs(((const float4*)(W_epsr + (size_t)row * NZ)) + tid);
            acc += dot4(a, ((const float4*)se)[tid]);
        } else if (tid < 128) {
            const int k = tid - 64;
            float4 a = __ldcs(((const float4*)(W_zr + (size_t)row * NZ)) + k);
            acc += dot4(a, ((const float4*)sz)[k]);
        } else if (tid < 160) {
            const int k = tid - 128;
            float4 a = __ldcs(((const float4*)(W_cr + (size_t)row * NC)) + k);
            acc += dot4(a, ((const float4*)sc)[k]);
        }
        racc[rr] = acc;
    }

    float4 acc4 = block_reduce4(make_float4(racc[0], racc[1], racc[2], racc[3]));
    if (tid == 0) {
        const float accs[4] = {acc4.x, acc4.y, acc4.z, acc4.w};
        #pragma unroll
        for (int rr = 0; rr < ROWS_B; rr++) {
            const int row = row0 + rr;
            float xv = x[row];
            float xn = xv + DT_ * (accs[rr] - xv);
            out[row] = xn;
            float rn = tanhf(xn + b[row]);
            out[N + row] = rn;
            g_rn[row] = rn;
        }
    }
}

// ---------------------------------------------------------------------------
// Kernel 3: z_new / c_new / eps_new. One block per output row: no cross-block
// finalize, no atomics, no fences. 512 threads, 4 contiguous float4 each.
// ---------------------------------------------------------------------------
__global__ void __launch_bounds__(512) k_tail(
    const float* __restrict__ W_rz, const float* __restrict__ W_rc,
    const float* __restrict__ z_tilde, float* __restrict__ out)
{
    const int idx = blockIdx.x;     // 0..383
    const float* __restrict__ Wrow = (idx < NZ)
        ? (W_rz + (size_t)idx * N)
        : (W_rc + (size_t)(idx - NZ) * N);
    const float4* __restrict__ w = (const float4*)Wrow;
    const float4* __restrict__ v = (const float4*)g_rn;
    const int base = threadIdx.x * 4;

    // Front-batched loads (MLP 8)
    float4 w0 = __ldcs(&w[base + 0]), w1 = __ldcs(&w[base + 1]);
    float4 w2 = __ldcs(&w[base + 2]), w3 = __ldcs(&w[base + 3]);
    float4 v0 = v[base + 0], v1 = v[base + 1];
    float4 v2 = v[base + 2], v3 = v[base + 3];

    float acc = (dot4(w0, v0) + dot4(w1, v1)) + (dot4(w2, v2) + dot4(w3, v3));
    acc = block_reduce_w(acc, 16);
    if (threadIdx.x == 0) {
        if (idx < NZ) {
            out[2 * N + idx] = acc;                          // z_new
            out[2 * N + NZ + NC + idx] = acc - z_tilde[idx]; // eps_new
        } else {
            out[2 * N + NZ + (idx - NZ)] = acc;              // c_new
        }
    }
}

extern "C" void kernel_launch(void* const* d_in, const int* in_sizes, int n_in,
                              void* d_out, int out_size) {
    // metadata order: x, eps, c, z_tilde, W_rr, W_zr, W_cr, W_epsr, W_rz, W_rc, b
    const float* x       = (const float*)d_in[0];
    const float* eps     = (const float*)d_in[1];
    const float* c       = (const float*)d_in[2];
    const float* z_tilde = (const float*)d_in[3];
    const float* W_rr    = (const float*)d_in[4];
    const float* W_zr    = (const float*)d_in[5];
    const float* W_cr    = (const float*)d_in[6];
    const float* W_epsr  = (const float*)d_in[7];
    const float* W_rz    = (const float*)d_in[8];
    const float* W_rc    = (const float*)d_in[9];
    const float* b       = (const float*)d_in[10];
    float* out = (float*)d_out;

    k_rz  <<<(NZ / 4) * SPL_A, 256>>>(x, b, W_rz);
    k_big <<<BIG_GRID, 256>>>(W_rr, W_zr, W_cr, W_epsr, x, eps, c, b, out);
    k_tail<<<NZ + NC, 512>>>(W_rz, W_rc, z_tilde, out);
}

// round 9
// speedup vs baseline: 1.3219x; 1.0807x over previous
#include <cuda_runtime.h>
#include <math.h>

#define N   8192
#define NZ  256
#define NC  128
#define DT_ 0.1f

// k_rz: z = W_rz @ r, 8-way column split, 4 rows per block -> 512 blocks
#define SPL_A 8
#define CHA4  (N / 4 / SPL_A)          // 256 float4 per column chunk

// Scratch (__device__ globals)
__device__ float g_r[N];
__device__ float g_zpart[SPL_A][NZ];
__device__ float g_rn[N];

// Fast tanh: 1 - 2/(exp(2x)+1). MUFU.EX2 + MUFU.RCP path, no branches.
// Saturates correctly at +/-inf; rel err ~1e-6 (vs 1e-3 test threshold).
__inline__ __device__ float ftanh(float x) {
    float e = __expf(2.0f * x);
    return 1.0f - __fdividef(2.0f, e + 1.0f);
}

__inline__ __device__ float dot4(float4 a, float4 b) {
    return a.x * b.x + a.y * b.y + a.z * b.z + a.w * b.w;
}

// Block reduce, up to 16 warps. Valid in thread 0.
__inline__ __device__ float block_reduce_w(float v, int nwarps) {
    __shared__ float sm[16];
    const int lane = threadIdx.x & 31;
    const int wid  = threadIdx.x >> 5;
    #pragma unroll
    for (int o = 16; o; o >>= 1) v += __shfl_down_sync(0xffffffffu, v, o);
    if (lane == 0) sm[wid] = v;
    __syncthreads();
    if (wid == 0) {
        v = (lane < nwarps) ? sm[lane] : 0.f;
        #pragma unroll
        for (int o = 8; o; o >>= 1) v += __shfl_down_sync(0xffffffffu, v, o);
    }
    return v;
}

// 4-wide block reduce, 8 warps (256 threads). Valid in thread 0.
__inline__ __device__ float4 block_reduce4(float4 v) {
    __shared__ float4 sm4[8];
    const int lane = threadIdx.x & 31;
    const int wid  = threadIdx.x >> 5;
    #pragma unroll
    for (int o = 16; o; o >>= 1) {
        v.x += __shfl_down_sync(0xffffffffu, v.x, o);
        v.y += __shfl_down_sync(0xffffffffu, v.y, o);
        v.z += __shfl_down_sync(0xffffffffu, v.z, o);
        v.w += __shfl_down_sync(0xffffffffu, v.w, o);
    }
    if (lane == 0) sm4[wid] = v;
    __syncthreads();
    if (wid == 0) {
        v = (lane < 8) ? sm4[lane] : make_float4(0.f, 0.f, 0.f, 0.f);
        #pragma unroll
        for (int o = 4; o; o >>= 1) {
            v.x += __shfl_down_sync(0xffffffffu, v.x, o);
            v.y += __shfl_down_sync(0xffffffffu, v.y, o);
            v.z += __shfl_down_sync(0xffffffffu, v.z, o);
            v.w += __shfl_down_sync(0xffffffffu, v.w, o);
        }
    }
    return v;
}

// ---------------------------------------------------------------------------
// Kernel 1: r = tanh(x+b) for split-owned chunks (row-group 0 persists g_r)
// + split-K partials of z = W_rz @ r for 4 rows/block.
// Grid: 64 row-groups * 8 splits = 512 blocks, 256 threads (1 float4/thread).
// ---------------------------------------------------------------------------
__global__ void __launch_bounds__(256) k_rz(
    const float* __restrict__ x, const float* __restrict__ b,
    const float* __restrict__ W_rz)
{
    const int s    = blockIdx.x & (SPL_A - 1);
    const int rg   = blockIdx.x >> 3;
    const int row0 = rg * 4;
    const int c4   = s * CHA4 + threadIdx.x;

    float4 xv = ((const float4*)x)[c4];
    float4 bv = ((const float4*)b)[c4];

    // Front-batch the 4 W loads (independent DRAM streams) before tanh math
    const float4* w0 = (const float4*)(W_rz + (size_t)(row0 + 0) * N);
    const float4* w1 = (const float4*)(W_rz + (size_t)(row0 + 1) * N);
    const float4* w2 = (const float4*)(W_rz + (size_t)(row0 + 2) * N);
    const float4* w3 = (const float4*)(W_rz + (size_t)(row0 + 3) * N);
    float4 a0 = __ldcs(&w0[c4]);
    float4 a1 = __ldcs(&w1[c4]);
    float4 a2 = __ldcs(&w2[c4]);
    float4 a3 = __ldcs(&w3[c4]);

    float4 r0;
    r0.x = ftanh(xv.x + bv.x); r0.y = ftanh(xv.y + bv.y);
    r0.z = ftanh(xv.z + bv.z); r0.w = ftanh(xv.w + bv.w);
    if (rg == 0) ((float4*)g_r)[c4] = r0;

    float4 acc = make_float4(dot4(a0, r0), dot4(a1, r0),
                             dot4(a2, r0), dot4(a3, r0));
    acc = block_reduce4(acc);
    if (threadIdx.x == 0) {
        g_zpart[s][row0 + 0] = acc.x;
        g_zpart[s][row0 + 1] = acc.y;
        g_zpart[s][row0 + 2] = acc.z;
        g_zpart[s][row0 + 3] = acc.w;
    }
}

// ---------------------------------------------------------------------------
// Kernel 2: fused row update, one row per block (R4 structure: g_r read
// directly, L1-hot across blocks on the same SM), with EXPLICITLY
// front-batched 8x LDG.128 for MLP=8.
// Grid: 8192 blocks, 256 threads.
// ---------------------------------------------------------------------------
__global__ void __launch_bounds__(256) k_big(
    const float* __restrict__ W_rr, const float* __restrict__ W_zr,
    const float* __restrict__ W_cr, const float* __restrict__ W_epsr,
    const float* __restrict__ x,    const float* __restrict__ eps,
    const float* __restrict__ c,    const float* __restrict__ b,
    float* __restrict__ out)
{
    const int row = blockIdx.x;
    const int t   = threadIdx.x;

    const float4* __restrict__ w = (const float4*)(W_rr + (size_t)row * N);
    const float4* __restrict__ v = (const float4*)g_r;

    // Front-batch all 8 weight loads (pure DRAM streams, independent)
    float4 wv[8];
    #pragma unroll
    for (int i = 0; i < 8; i++) wv[i] = __ldcs(&w[t + i * 256]);

    float a0 = 0.f, a1 = 0.f, a2 = 0.f, a3 = 0.f;
    #pragma unroll
    for (int i = 0; i < 8; i++) {
        float d = dot4(wv[i], v[t + i * 256]);   // v: L1-hit after first block
        if ((i & 3) == 0) a0 += d;
        else if ((i & 3) == 1) a1 += d;
        else if ((i & 3) == 2) a2 += d;
        else a3 += d;
    }
    float acc = (a0 + a1) + (a2 + a3);

    // Side dots on disjoint thread ranges (640 extra elems per row)
    if (t < 64) {                               // W_epsr row · eps
        float4 a = __ldcs(((const float4*)(W_epsr + (size_t)row * NZ)) + t);
        acc += dot4(a, ((const float4*)eps)[t]);
    } else if (t < 128) {                       // W_zr row · z (sum split partials)
        const int k = t - 64;
        float4 a = __ldcs(((const float4*)(W_zr + (size_t)row * NZ)) + k);
        float4 q = ((const float4*)g_zpart[0])[k];
        #pragma unroll
        for (int s = 1; s < SPL_A; s++) {
            float4 p = ((const float4*)g_zpart[s])[k];
            q.x += p.x; q.y += p.y; q.z += p.z; q.w += p.w;
        }
        acc += dot4(a, q);
    } else if (t < 160) {                       // W_cr row · c
        const int k = t - 128;
        float4 a = __ldcs(((const float4*)(W_cr + (size_t)row * NC)) + k);
        acc += dot4(a, ((const float4*)c)[k]);
    }

    acc = block_reduce_w(acc, 8);
    if (t == 0) {
        float xv = x[row];
        float xn = xv + DT_ * (acc - xv);
        out[row] = xn;
        float rn = ftanh(xn + b[row]);
        out[N + row] = rn;
        g_rn[row] = rn;
    }
}

// ---------------------------------------------------------------------------
// Kernel 3: z_new / c_new / eps_new. One block per output row, 512 threads,
// 4 contiguous float4 each, front-batched. No atomics, no fences.
// ---------------------------------------------------------------------------
__global__ void __launch_bounds__(512) k_tail(
    const float* __restrict__ W_rz, const float* __restrict__ W_rc,
    const float* __restrict__ z_tilde, float* __restrict__ out)
{
    const int idx = blockIdx.x;     // 0..383
    const float* __restrict__ Wrow = (idx < NZ)
        ? (W_rz + (size_t)idx * N)
        : (W_rc + (size_t)(idx - NZ) * N);
    const float4* __restrict__ w = (const float4*)Wrow;
    const float4* __restrict__ v = (const float4*)g_rn;
    const int base = threadIdx.x * 4;

    float4 w0 = __ldcs(&w[base + 0]), w1 = __ldcs(&w[base + 1]);
    float4 w2 = __ldcs(&w[base + 2]), w3 = __ldcs(&w[base + 3]);
    float4 v0 = v[base + 0], v1 = v[base + 1];
    float4 v2 = v[base + 2], v3 = v[base + 3];

    float acc = (dot4(w0, v0) + dot4(w1, v1)) + (dot4(w2, v2) + dot4(w3, v3));
    acc = block_reduce_w(acc, 16);
    if (threadIdx.x == 0) {
        if (idx < NZ) {
            out[2 * N + idx] = acc;                          // z_new
            out[2 * N + NZ + NC + idx] = acc - z_tilde[idx]; // eps_new
        } else {
            out[2 * N + NZ + (idx - NZ)] = acc;              // c_new
        }
    }
}

extern "C" void kernel_launch(void* const* d_in, const int* in_sizes, int n_in,
                              void* d_out, int out_size) {
    // metadata order: x, eps, c, z_tilde, W_rr, W_zr, W_cr, W_epsr, W_rz, W_rc, b
    const float* x       = (const float*)d_in[0];
    const float* eps     = (const float*)d_in[1];
    const float* c       = (const float*)d_in[2];
    const float* z_tilde = (const float*)d_in[3];
    const float* W_rr    = (const float*)d_in[4];
    const float* W_zr    = (const float*)d_in[5];
    const float* W_cr    = (const float*)d_in[6];
    const float* W_epsr  = (const float*)d_in[7];
    const float* W_rz    = (const float*)d_in[8];
    const float* W_rc    = (const float*)d_in[9];
    const float* b       = (const float*)d_in[10];
    float* out = (float*)d_out;

    k_rz  <<<(NZ / 4) * SPL_A, 256>>>(x, b, W_rz);
    k_big <<<N, 256>>>(W_rr, W_zr, W_cr, W_epsr, x, eps, c, b, out);
    k_tail<<<NZ + NC, 512>>>(W_rz, W_rc, z_tilde, out);
}